// round 2
// baseline (speedup 1.0000x reference)
#include <cuda_runtime.h>

namespace {

constexpr int NQ = 14;
constexpr int NS = 1 << NQ;          // 16384 amplitudes
constexpr int NT = 512;              // threads per CTA
constexpr int NPAD = NS + (NS >> 3); // padded state (bank-conflict fix)

struct Smem {
    float2 st[NPAD];
    float icb[NQ], isb[NQ], rzb[NQ];  // RX1 cos/sin, RZ theta (bit-position indexed)
    float pc[28], ps[28];             // gate cos/sin: [0..13] IsingXX(cp), [14..27] RX3
    float red[(NT / 32) * NQ];
};

// padded physical address: i + i/8 (spreads high index bits into bank bits)
__device__ __forceinline__ int PH(int i) { return i + (i >> 3); }

__host__ __device__ constexpr int hb(int m) {
    int r = 0; while (m > 1) { m >>= 1; ++r; } return r;
}

template<int... Ms>
__host__ __device__ constexpr int selmask() {
    int s = 0;
    const int a[] = {Ms...};
    for (unsigned i = 0; i < sizeof...(Ms); ++i) s |= 1 << hb(a[i]);
    return s;
}

// Apply G commuting butterfly gates (RX: 1-bit mask, IsingXX: 2-bit mask).
// Each gate: pair (i, i^m): new_i = c*a_i + (-i*s)*a_{i^m}  (and symmetric).
template<bool DoRZ, int... Ms>
__device__ __forceinline__ void butterfly_pass(Smem* sm, int pcBase) {
    constexpr int G = sizeof...(Ms);
    constexpr int NO = 1 << G;
    constexpr int masks[G] = {Ms...};
    constexpr int SMK = selmask<Ms...>();   // one selector bit per gate (highest mask bit)
    constexpr int NGRP = NS >> G;

    float cg[G], sg[G];
#pragma unroll
    for (int g = 0; g < G; ++g) { cg[g] = sm->pc[pcBase + g]; sg[g] = sm->ps[pcBase + g]; }

    for (int k = threadIdx.x; k < NGRP; k += NT) {
        // representative index: scatter k's bits into non-selector positions
        int rep = 0, kk = k;
#pragma unroll
        for (int pos = 0; pos < NQ; ++pos) {
            if (!((SMK >> pos) & 1)) { rep |= (kk & 1) << pos; kk >>= 1; }
        }
        int idx[NO];
#pragma unroll
        for (int t = 0; t < NO; ++t) {
            int x = rep;
#pragma unroll
            for (int g = 0; g < G; ++g) if ((t >> g) & 1) x ^= masks[g];
            idx[t] = x;
        }
        float2 a[NO];
#pragma unroll
        for (int t = 0; t < NO; ++t) a[t] = sm->st[PH(idx[t])];

#pragma unroll
        for (int g = 0; g < G; ++g) {
            const float c = cg[g], s = sg[g];
#pragma unroll
            for (int t = 0; t < NO; ++t) {
                if (!((t >> g) & 1)) {
                    const int u = t | (1 << g);
                    const float2 a0 = a[t], a1 = a[u];
                    a[t] = make_float2(fmaf(c, a0.x,  s * a1.y), fmaf(c, a0.y, -s * a1.x));
                    a[u] = make_float2(fmaf(c, a1.x,  s * a0.y), fmaf(c, a1.y, -s * a0.x));
                }
            }
        }
        if (DoRZ) {  // fold the full diagonal RZ layer into this pass's epilogue
#pragma unroll
            for (int t = 0; t < NO; ++t) {
                float ang = 0.f;
#pragma unroll
                for (int bp = 0; bp < NQ; ++bp)
                    ang += ((idx[t] >> bp) & 1) ? 0.5f * sm->rzb[bp] : -0.5f * sm->rzb[bp];
                float sa, ca;
                sincosf(ang, &sa, &ca);
                const float2 v = a[t];
                a[t] = make_float2(v.x * ca - v.y * sa, v.x * sa + v.y * ca);
            }
        }
#pragma unroll
        for (int t = 0; t < NO; ++t) sm->st[PH(idx[t])] = a[t];
    }
}

__global__ __launch_bounds__(NT, 1)
void qsim_kernel(const float* __restrict__ cp, const float* __restrict__ p,
                 float* __restrict__ out) {
    extern __shared__ char smraw[];
    Smem* sm = reinterpret_cast<Smem*>(smraw);
    const int tid = threadIdx.x;
    const int b = blockIdx.x;

    if (tid < NQ) {
        const int w = tid;
        float sn, cs;
        sincosf(0.5f * p[(b * 3 + 0) * NQ + w], &sn, &cs);   // RX layer 1
        sm->icb[NQ - 1 - w] = cs; sm->isb[NQ - 1 - w] = sn;
        sincosf(0.5f * cp[b * NQ + w], &sn, &cs);            // all 14 IsingXX angles
        sm->pc[w] = cs; sm->ps[w] = sn;
        sm->rzb[NQ - 1 - w] = p[(b * 3 + 1) * NQ + w];       // RZ thetas
        sincosf(0.5f * p[(b * 3 + 2) * NQ + w], &sn, &cs);   // RX layer 3
        sm->pc[14 + w] = cs; sm->ps[14 + w] = sn;
    }
    __syncthreads();

    // --- Init = RX layer 1 applied to |0...0> (tensor product, pointwise) ---
    for (int i = tid; i < NS; i += NT) {
        float mag = 1.f;
#pragma unroll
        for (int bp = 0; bp < NQ; ++bp)
            mag *= ((i >> bp) & 1) ? sm->isb[bp] : sm->icb[bp];
        const int k4 = __popc(i) & 3;   // (-i)^popc
        float2 v;
        v.x = (k4 == 0) ? mag : ((k4 == 2) ? -mag : 0.f);
        v.y = (k4 == 1) ? -mag : ((k4 == 3) ? mag : 0.f);
        sm->st[PH(i)] = v;
    }
    __syncthreads();

    // IsingXX layer 1: qubit pairs (0,1)..(12,13) -> bit-pair masks
    butterfly_pass<false, 0x3000, 0x0C00, 0x0300, 0x00C0>(sm, 0);
    __syncthreads();
    butterfly_pass<true,  0x0030, 0x000C, 0x0003>(sm, 4);    // + fused RZ layer
    __syncthreads();
    // IsingXX layer 2: pairs (1,2)..(11,12),(13,0)
    butterfly_pass<false, 0x1800, 0x0600, 0x0180, 0x0060>(sm, 7);
    __syncthreads();
    butterfly_pass<false, 0x0018, 0x0006, 0x2001>(sm, 11);
    __syncthreads();
    // RX layer 3: 14 single-qubit gates
    butterfly_pass<false, 0x2000, 0x1000, 0x0800, 0x0400>(sm, 14);
    __syncthreads();
    butterfly_pass<false, 0x0200, 0x0100, 0x0080, 0x0040>(sm, 18);
    __syncthreads();
    butterfly_pass<false, 0x0020, 0x0010, 0x0008>(sm, 22);
    __syncthreads();
    butterfly_pass<false, 0x0004, 0x0002, 0x0001>(sm, 25);
    __syncthreads();

    // --- Final: composed MCX permutation + |amp|^2 + Z-sign reduction ---
    float acc[NQ];
#pragma unroll
    for (int w = 0; w < NQ; ++w) acc[w] = 0.f;

    for (int i = tid; i < NS; i += NT) {
        int j = i;
#pragma unroll
        for (int w = NQ - 1; w >= 0; --w) {   // composite = P0(P1(...P13(i)))
            const int c1 = NQ - 1 - w;
            const int c2 = NQ - 1 - ((w + 1) % NQ);
            const int tt = NQ - 1 - ((w + 2) % NQ);
            const int b1 = (j >> c1) & 1;
            const int b2 = (j >> c2) & 1;
            if (b1 & (b2 ^ 1)) j ^= (1 << tt);
        }
        const float2 aa = sm->st[PH(j)];
        const float pr = fmaf(aa.x, aa.x, aa.y * aa.y);
#pragma unroll
        for (int w = 0; w < NQ; ++w)
            acc[w] += ((i >> (NQ - 1 - w)) & 1) ? -pr : pr;
    }

#pragma unroll
    for (int w = 0; w < NQ; ++w)
#pragma unroll
        for (int off = 16; off > 0; off >>= 1)
            acc[w] += __shfl_xor_sync(0xffffffffu, acc[w], off);

    const int warp = tid >> 5, lane = tid & 31;
    if (lane == 0) {
#pragma unroll
        for (int w = 0; w < NQ; ++w) sm->red[warp * NQ + w] = acc[w];
    }
    __syncthreads();
    if (tid < NQ) {
        float s = 0.f;
#pragma unroll
        for (int ww = 0; ww < NT / 32; ++ww) s += sm->red[ww * NQ + tid];
        out[b * NQ + tid] = s;
    }
}

} // namespace

extern "C" void kernel_launch(void* const* d_in, const int* in_sizes, int n_in,
                              void* d_out, int out_size) {
    const float* cp = (const float*)d_in[0];
    const float* p  = (const float*)d_in[1];
    float* out = (float*)d_out;
    const int B = in_sizes[0] / NQ;   // 512
    cudaFuncSetAttribute(qsim_kernel, cudaFuncAttributeMaxDynamicSharedMemorySize,
                         (int)sizeof(Smem));
    qsim_kernel<<<B, NT, sizeof(Smem)>>>(cp, p, out);
}

// round 3
// speedup vs baseline: 1.8186x; 1.8186x over previous
#include <cuda_runtime.h>
#include <stdint.h>

namespace {

constexpr int NQ = 14;
constexpr int NS = 1 << NQ;          // 16384 amplitudes
constexpr int NT = 512;              // threads per CTA
constexpr int NPAD = NS + (NS >> 3); // padded state (bank-conflict fix)

struct Smem {
    float2 st[NPAD];
    float2 U[128], V[128];            // RZ phase factor tables (bits 0-6 / 7-13)
    float icb[NQ], isb[NQ];           // RX1 cos/sin per bit position
    float rc[NQ], rs[NQ];             // RZ half-angle cos/sin per bit position
    float pc[28], ps[28];             // gate cos/sin by pass-slot
    float red[(NT / 32) * NQ];
};

__device__ uint16_t g_inv[NS];       // inverse of the composed MCX permutation

// padded physical address: spreads high index bits into bank bits
__device__ __forceinline__ int PH(int i) { return i + (i >> 3); }

__device__ __forceinline__ float2 cmul(float2 a, float2 b) {
    return make_float2(fmaf(a.x, b.x, -a.y * b.y), fmaf(a.x, b.y, a.y * b.x));
}

// cp column w -> coefficient slot; RX3 qubit w -> coefficient slot
__constant__ int CP_SLOT[14] = {0,1,2,3,4,5,6,19,20,25,14,7,8,13};
__constant__ int RX_SLOT[14] = {15,21,22,23,24,26,27,17,18,9,10,11,12,16};

// Build orbit indices: scatter k over non-selector bits, XOR generator combos.
template<int G, int SMK>
__device__ __forceinline__ int make_idx(int k, const int (&gens)[G], int (&idx)[1 << G]) {
    int rep = 0;
#pragma unroll
    for (int pos = 0; pos < NQ; ++pos)
        if (!((SMK >> pos) & 1)) { rep |= (k & 1) << pos; k >>= 1; }
#pragma unroll
    for (int t = 0; t < (1 << G); ++t) {
        int x = rep;
#pragma unroll
        for (int g = 0; g < G; ++g) if ((t >> g) & 1) x ^= gens[g];
        idx[t] = x;
    }
    return rep;
}

// Apply NG butterfly gates; gate g pairs t <-> t^combos[g] (combo = mask over gen dims).
// RX and IsingXX share the matrix [c, -is; -is, c].
template<int G, int NG>
__device__ __forceinline__ void apply_gates(float2 (&a)[1 << G], const int (&combos)[NG],
                                            const float (&cg)[NG], const float (&sg)[NG]) {
#pragma unroll
    for (int g = 0; g < NG; ++g) {
        const int cb = combos[g];
        const int lb = cb & (-cb);
        const float c = cg[g], s = sg[g];
#pragma unroll
        for (int t = 0; t < (1 << G); ++t) {
            if ((t & lb) == 0) {
                const int u = t ^ cb;
                const float2 a0 = a[t], a1 = a[u];
                a[t] = make_float2(fmaf(c, a0.x,  s * a1.y), fmaf(c, a0.y, -s * a1.x));
                a[u] = make_float2(fmaf(c, a1.x,  s * a0.y), fmaf(c, a1.y, -s * a0.x));
            }
        }
    }
}

// Generic load-gates-(RZ)-store pass.
template<int G, int NG, int SMK, bool DoRZ>
__device__ __forceinline__ void run_pass(Smem* sm, const int (&gens)[G],
                                         const int (&combos)[NG], const int (&slots)[NG]) {
    constexpr int NO = 1 << G;
    float cg[NG], sg[NG];
#pragma unroll
    for (int g = 0; g < NG; ++g) { cg[g] = sm->pc[slots[g]]; sg[g] = sm->ps[slots[g]]; }
    for (int k = threadIdx.x; k < (NS >> G); k += NT) {
        int idx[NO];
        make_idx<G, SMK>(k, gens, idx);
        float2 a[NO];
#pragma unroll
        for (int t = 0; t < NO; ++t) a[t] = sm->st[PH(idx[t])];
        apply_gates<G, NG>(a, combos, cg, sg);
        if (DoRZ) {
#pragma unroll
            for (int t = 0; t < NO; ++t) {
                const float2 ph = cmul(sm->U[idx[t] & 127], sm->V[idx[t] >> 7]);
                a[t] = cmul(a[t], ph);
            }
        }
#pragma unroll
        for (int t = 0; t < NO; ++t) sm->st[PH(idx[t])] = a[t];
    }
}

// Pass 1: init state (RX layer 1 on |0>) in registers + XX layer-1 gates (high pairs).
__device__ __forceinline__ void run_pass1(Smem* sm) {
    constexpr int gens[4] = {0x3000, 0x0C00, 0x0300, 0x00C0};
    constexpr int SMK = 0x2A80;                 // selectors: bits 13,11,9,7
    constexpr int hi[4] = {13, 11, 9, 7};
    constexpr int lo[4] = {12, 10, 8, 6};
    constexpr int combos[4] = {1, 2, 4, 8};
    constexpr int slots[4]  = {0, 1, 2, 3};
    float cg[4], sg[4];
#pragma unroll
    for (int g = 0; g < 4; ++g) { cg[g] = sm->pc[slots[g]]; sg[g] = sm->ps[slots[g]]; }
    float cbr[NQ], sbr[NQ];
#pragma unroll
    for (int bb = 0; bb < NQ; ++bb) { cbr[bb] = sm->icb[bb]; sbr[bb] = sm->isb[bb]; }

    for (int k = threadIdx.x; k < (NS >> 4); k += NT) {
        int idx[16];
        const int rep = make_idx<4, SMK>(k, gens, idx);
        // separable init amplitude: base over non-span bits 0..5
        float base = 1.f;
#pragma unroll
        for (int bb = 0; bb < 6; ++bb)
            base *= ((rep >> bb) & 1) ? sbr[bb] : cbr[bb];
        // per-gate orbit factors; sign of popc change folded into f1
        float f0[4], f1[4];
#pragma unroll
        for (int g = 0; g < 4; ++g) {
            const int x = (rep >> lo[g]) & 1;
            f0[g] = cbr[hi[g]] * (x ? sbr[lo[g]] : cbr[lo[g]]);
            const float m1 = sbr[hi[g]] * (x ? cbr[lo[g]] : sbr[lo[g]]);
            f1[g] = x ? m1 : -m1;                    // 00->11 flips popc by 2 -> sign -1
        }
        const float p01[4] = {f0[0]*f0[1], f1[0]*f0[1], f0[0]*f1[1], f1[0]*f1[1]};
        const float p23[4] = {f0[2]*f0[3], f1[2]*f0[3], f0[2]*f1[3], f1[2]*f1[3]};
        const int k4 = __popc(rep) & 3;              // (-i)^popc
        float2 a[16];
#pragma unroll
        for (int t = 0; t < 16; ++t) {
            const float m = base * p01[t & 3] * p23[t >> 2];
            float2 v;
            v.x = (k4 == 0) ? m : ((k4 == 2) ? -m : 0.f);
            v.y = (k4 == 1) ? -m : ((k4 == 3) ? m : 0.f);
            a[t] = v;
        }
        apply_gates<4, 4>(a, combos, cg, sg);
#pragma unroll
        for (int t = 0; t < 16; ++t) sm->st[PH(idx[t])] = a[t];
    }
}

// Pass D: last gates + fused |amp|^2 via inverse-permutation table + Z-sign accumulation.
__device__ __forceinline__ void run_passD(Smem* sm, float (&acc)[NQ]) {
    constexpr int gens[2] = {0x180, 0x100};
    constexpr int SMK = 0x180;                       // selectors: bits 7, 8
    constexpr int combos[3] = {1, 2, 3};             // XX 0x180, RX 0x100, RX 0x80
    constexpr int slots[3]  = {25, 26, 27};
    float cg[3], sg[3];
#pragma unroll
    for (int g = 0; g < 3; ++g) { cg[g] = sm->pc[slots[g]]; sg[g] = sm->ps[slots[g]]; }
    for (int k = threadIdx.x; k < (NS >> 2); k += NT) {
        int idx[4];
        make_idx<2, SMK>(k, gens, idx);
        float2 a[4];
#pragma unroll
        for (int t = 0; t < 4; ++t) a[t] = sm->st[PH(idx[t])];
        apply_gates<2, 3>(a, combos, cg, sg);
#pragma unroll
        for (int t = 0; t < 4; ++t) {
            const float pr = fmaf(a[t].x, a[t].x, a[t].y * a[t].y);
            const int i = (int)g_inv[idx[t]];
#pragma unroll
            for (int w = 0; w < NQ; ++w)
                acc[w] += ((i >> (NQ - 1 - w)) & 1) ? -pr : pr;
        }
    }
}

__global__ void build_inv_kernel() {
    const int i = blockIdx.x * blockDim.x + threadIdx.x;
    int j = i;
#pragma unroll
    for (int w = NQ - 1; w >= 0; --w) {
        const int c1 = NQ - 1 - w;
        const int c2 = NQ - 1 - ((w + 1) % NQ);
        const int tt = NQ - 1 - ((w + 2) % NQ);
        const int b1 = (j >> c1) & 1;
        const int b2 = (j >> c2) & 1;
        if (b1 & (b2 ^ 1)) j ^= (1 << tt);
    }
    g_inv[j] = (uint16_t)i;   // composite(i) = j  =>  inv[j] = i (bijection, no race)
}

__global__ __launch_bounds__(NT, 1)
void qsim_kernel(const float* __restrict__ cp, const float* __restrict__ p,
                 float* __restrict__ out) {
    extern __shared__ char smraw[];
    Smem* sm = reinterpret_cast<Smem*>(smraw);
    const int tid = threadIdx.x;
    const int b = blockIdx.x;

    if (tid < NQ) {
        const int w = tid;
        float sn, cs;
        sincosf(0.5f * p[(b * 3 + 0) * NQ + w], &sn, &cs);   // RX layer 1
        sm->icb[NQ - 1 - w] = cs; sm->isb[NQ - 1 - w] = sn;
        sincosf(0.5f * cp[b * NQ + w], &sn, &cs);            // IsingXX angles
        const int sl = CP_SLOT[w];
        sm->pc[sl] = cs; sm->ps[sl] = sn;
        sincosf(0.5f * p[(b * 3 + 1) * NQ + w], &sn, &cs);   // RZ half-angles
        sm->rc[NQ - 1 - w] = cs; sm->rs[NQ - 1 - w] = sn;
        sincosf(0.5f * p[(b * 3 + 2) * NQ + w], &sn, &cs);   // RX layer 3
        const int s2 = RX_SLOT[w];
        sm->pc[s2] = cs; sm->ps[s2] = sn;
    }
    __syncthreads();

    // Build RZ phase tables (threads 0-255) while all threads run pass 1.
    if (tid < 256) {
        const int half = tid >> 7;
        const int k = tid & 127;
        const int bb = half * 7;
        float2 accp = make_float2(1.f, 0.f);
#pragma unroll
        for (int q = 0; q < 7; ++q) {
            const float c = sm->rc[bb + q], s = sm->rs[bb + q];
            const float2 f = make_float2(c, ((k >> q) & 1) ? s : -s);
            accp = cmul(accp, f);
        }
        (half ? sm->V : sm->U)[k] = accp;
    }

    run_pass1(sm);                                    // init + XX1 high pairs
    __syncthreads();

    {   // XX1 low pairs + full RZ layer (table-based)
        constexpr int gens[3] = {0x30, 0x0C, 0x03};
        constexpr int combos[3] = {1, 2, 4};
        constexpr int slots[3]  = {4, 5, 6};
        run_pass<3, 3, 0x2A, true>(sm, gens, combos, slots);
    }
    __syncthreads();

    {   // Pass A: XX (9,10),(11,12) + RX q9,q10,q11,q12
        constexpr int gens[4] = {0x18, 0x10, 0x06, 0x04};
        constexpr int combos[6] = {1, 4, 2, 3, 8, 12};
        constexpr int slots[6]  = {7, 8, 9, 10, 11, 12};
        run_pass<4, 6, 0x1E, false>(sm, gens, combos, slots);
    }
    __syncthreads();

    {   // Pass B: XX (13,0),(7,8) + RX q0,q13,q7,q8
        constexpr int gens[4] = {0x2001, 0x2000, 0x60, 0x40};
        constexpr int combos[6] = {1, 4, 2, 3, 8, 12};
        constexpr int slots[6]  = {13, 14, 15, 16, 17, 18};
        run_pass<4, 6, 0x2061, false>(sm, gens, combos, slots);
    }
    __syncthreads();

    {   // Pass C: XX (1,2),(3,4) + RX q1,q2,q3,q4
        constexpr int gens[4] = {0x1800, 0x1000, 0x600, 0x400};
        constexpr int combos[6] = {1, 4, 2, 3, 8, 12};
        constexpr int slots[6]  = {19, 20, 21, 22, 23, 24};
        run_pass<4, 6, 0x1E00, false>(sm, gens, combos, slots);
    }
    __syncthreads();

    // Pass D: XX (5,6) + RX q5,q6 + fused permuted probability reduction
    float acc[NQ];
#pragma unroll
    for (int w = 0; w < NQ; ++w) acc[w] = 0.f;
    run_passD(sm, acc);

#pragma unroll
    for (int w = 0; w < NQ; ++w)
#pragma unroll
        for (int off = 16; off > 0; off >>= 1)
            acc[w] += __shfl_xor_sync(0xffffffffu, acc[w], off);

    const int warp = tid >> 5, lane = tid & 31;
    if (lane == 0) {
#pragma unroll
        for (int w = 0; w < NQ; ++w) sm->red[warp * NQ + w] = acc[w];
    }
    __syncthreads();
    if (tid < NQ) {
        float s = 0.f;
#pragma unroll
        for (int ww = 0; ww < NT / 32; ++ww) s += sm->red[ww * NQ + tid];
        out[b * NQ + tid] = s;
    }
}

} // namespace

extern "C" void kernel_launch(void* const* d_in, const int* in_sizes, int n_in,
                              void* d_out, int out_size) {
    const float* cp = (const float*)d_in[0];
    const float* p  = (const float*)d_in[1];
    float* out = (float*)d_out;
    const int B = in_sizes[0] / NQ;   // 512
    build_inv_kernel<<<NS / NT, NT>>>();
    cudaFuncSetAttribute(qsim_kernel, cudaFuncAttributeMaxDynamicSharedMemorySize,
                         (int)sizeof(Smem));
    qsim_kernel<<<B, NT, sizeof(Smem)>>>(cp, p, out);
}

// round 4
// speedup vs baseline: 2.5590x; 1.4071x over previous
#include <cuda_runtime.h>
#include <stdint.h>

namespace {

constexpr int NQ = 14;
constexpr int NS = 1 << NQ;          // 16384 amplitudes
constexpr int NT = 512;              // threads per CTA
constexpr int NPAD = NS + (NS >> 3); // padded state (bank-conflict fix)

struct Smem {
    float2 st[NPAD];
    float2 T[7][4];                   // pair tables: prefix circuit (RX1+XX1+RZ) per bit-pair
    float pc[21], ps[21];             // gate cos/sin: slots 0-6 XX2 (cp col 7+s), 7-20 RX3 (qubit s-7)
    float red[(NT / 32) * NQ];
};

__device__ uint16_t g_inv[NS];       // inverse of the composed MCX permutation

__device__ __forceinline__ int PH(int i) { return i + (i >> 3); }

__device__ __forceinline__ float2 cmul(float2 a, float2 b) {
    return make_float2(fmaf(a.x, b.x, -a.y * b.y), fmaf(a.x, b.y, a.y * b.x));
}

// Build orbit indices: scatter k over non-selector bits, XOR generator combos.
template<int G, int SMK>
__device__ __forceinline__ int make_idx(int k, const int (&gens)[G], int (&idx)[1 << G]) {
    int rep = 0;
#pragma unroll
    for (int pos = 0; pos < NQ; ++pos)
        if (!((SMK >> pos) & 1)) { rep |= (k & 1) << pos; k >>= 1; }
#pragma unroll
    for (int t = 0; t < (1 << G); ++t) {
        int x = rep;
#pragma unroll
        for (int g = 0; g < G; ++g) if ((t >> g) & 1) x ^= gens[g];
        idx[t] = x;
    }
    return rep;
}

// Apply NG butterfly gates; gate g pairs t <-> t^combos[g] (combo = mask over gen dims).
template<int G, int NG>
__device__ __forceinline__ void apply_gates(float2 (&a)[1 << G], const int (&combos)[NG],
                                            const float (&cg)[NG], const float (&sg)[NG]) {
#pragma unroll
    for (int g = 0; g < NG; ++g) {
        const int cb = combos[g];
        const int lb = cb & (-cb);
        const float c = cg[g], s = sg[g];
#pragma unroll
        for (int t = 0; t < (1 << G); ++t) {
            if ((t & lb) == 0) {
                const int u = t ^ cb;
                const float2 a0 = a[t], a1 = a[u];
                a[t] = make_float2(fmaf(c, a0.x,  s * a1.y), fmaf(c, a0.y, -s * a1.x));
                a[u] = make_float2(fmaf(c, a1.x,  s * a0.y), fmaf(c, a1.y, -s * a0.x));
            }
        }
    }
}

// Generic load-gates-store pass.
template<int G, int NG, int SMK>
__device__ __forceinline__ void run_pass(Smem* sm, const int (&gens)[G],
                                         const int (&combos)[NG], const int (&slots)[NG]) {
    constexpr int NO = 1 << G;
    float cg[NG], sg[NG];
#pragma unroll
    for (int g = 0; g < NG; ++g) { cg[g] = sm->pc[slots[g]]; sg[g] = sm->ps[slots[g]]; }
    for (int k = threadIdx.x; k < (NS >> G); k += NT) {
        int idx[NO];
        make_idx<G, SMK>(k, gens, idx);
        float2 a[NO];
#pragma unroll
        for (int t = 0; t < NO; ++t) a[t] = sm->st[PH(idx[t])];
        apply_gates<G, NG>(a, combos, cg, sg);
#pragma unroll
        for (int t = 0; t < NO; ++t) sm->st[PH(idx[t])] = a[t];
    }
}

// Pass A: generate state from pair tables (prefix circuit is a tensor product
// over bit-pairs) + XX(9,10), XX(11,12), RX q9..q12. First write to smem state.
__device__ __forceinline__ void run_passA(Smem* sm) {
    constexpr int gens[4] = {0x18, 0x10, 0x06, 0x04};
    constexpr int SMK = 0x1E;                       // span: bits 1-4
    constexpr int combos[6] = {1, 4, 2, 3, 8, 12};  // XX(9,10),XX(11,12),RX q9,q10,q11,q12
    constexpr int slots[6]  = {4, 5, 16, 17, 18, 19};
    float cg[6], sg[6];
#pragma unroll
    for (int g = 0; g < 6; ++g) { cg[g] = sm->pc[slots[g]]; sg[g] = sm->ps[slots[g]]; }

    for (int k = threadIdx.x; k < (NS >> 4); k += NT) {
        int idx[16];
        const int rep = make_idx<4, SMK>(k, gens, idx);
        // amp(i) = prod_m T_m[(i>>2m)&3]; bits 6-13 fixed by rep
        const float2 base = cmul(cmul(sm->T[3][(rep >> 6) & 3], sm->T[4][(rep >> 8) & 3]),
                                 cmul(sm->T[5][(rep >> 10) & 3], sm->T[6][(rep >> 12) & 3]));
        const int b0 = rep & 1, b5 = (rep >> 5) & 1;
        const float2 q2[2] = { cmul(base, sm->T[2][2 * b5]),
                               cmul(base, sm->T[2][1 + 2 * b5]) };  // bit4 = 0/1
        const float2 q0[2] = { sm->T[0][b0], sm->T[0][b0 + 2] };    // bit1 = 0/1
        float2 a[16];
#pragma unroll
        for (int t = 0; t < 16; ++t) {
            const int j = idx[t];   // in-span bits are compile-time constants per t
            a[t] = cmul(cmul(q2[(j >> 4) & 1], sm->T[1][(j >> 2) & 3]), q0[(j >> 1) & 1]);
        }
        apply_gates<4, 6>(a, combos, cg, sg);
#pragma unroll
        for (int t = 0; t < 16; ++t) sm->st[PH(idx[t])] = a[t];
    }
}

// Pass D: XX(5,6) + RX q5,q6 + fused |amp|^2 via inverse-permutation + Z-sign acc.
__device__ __forceinline__ void run_passD(Smem* sm, float (&acc)[NQ]) {
    constexpr int gens[2] = {0x180, 0x100};
    constexpr int SMK = 0x180;                      // span: bits 7,8
    constexpr int combos[3] = {1, 2, 3};            // XX(5,6), RX q5, RX q6
    constexpr int slots[3]  = {2, 12, 13};
    float cg[3], sg[3];
#pragma unroll
    for (int g = 0; g < 3; ++g) { cg[g] = sm->pc[slots[g]]; sg[g] = sm->ps[slots[g]]; }
#pragma unroll 2
    for (int k = threadIdx.x; k < (NS >> 2); k += NT) {
        int idx[4];
        make_idx<2, SMK>(k, gens, idx);
        float2 a[4];
#pragma unroll
        for (int t = 0; t < 4; ++t) a[t] = sm->st[PH(idx[t])];
        apply_gates<2, 3>(a, combos, cg, sg);
#pragma unroll
        for (int t = 0; t < 4; ++t) {
            const float pr = fmaf(a[t].x, a[t].x, a[t].y * a[t].y);
            const int i = (int)__ldg(&g_inv[idx[t]]);
#pragma unroll
            for (int w = 0; w < NQ; ++w)
                acc[w] += ((i >> (NQ - 1 - w)) & 1) ? -pr : pr;
        }
    }
}

__global__ void build_inv_kernel() {
    const int i = blockIdx.x * blockDim.x + threadIdx.x;
    int j = i;
#pragma unroll
    for (int w = NQ - 1; w >= 0; --w) {
        const int c1 = NQ - 1 - w;
        const int c2 = NQ - 1 - ((w + 1) % NQ);
        const int tt = NQ - 1 - ((w + 2) % NQ);
        const int b1 = (j >> c1) & 1;
        const int b2 = (j >> c2) & 1;
        if (b1 & (b2 ^ 1)) j ^= (1 << tt);
    }
    g_inv[j] = (uint16_t)i;   // composite(i) = j  =>  inv[j] = i (bijection, no race)
}

__global__ __launch_bounds__(NT, 1)
void qsim_kernel(const float* __restrict__ cp, const float* __restrict__ p,
                 float* __restrict__ out) {
    extern __shared__ char smraw[];
    Smem* sm = reinterpret_cast<Smem*>(smraw);
    const int tid = threadIdx.x;
    const int b = blockIdx.x;

    // Gate coefficient slots: XX2 (cp cols 7-13 -> slots 0-6), RX3 (qubit w -> slot 7+w)
    if (tid < NQ) {
        const int w = tid;
        float sn, cs;
        if (w >= 7) {
            sincosf(0.5f * cp[b * NQ + w], &sn, &cs);
            sm->pc[w - 7] = cs; sm->ps[w - 7] = sn;
        }
        sincosf(0.5f * p[(b * 3 + 2) * NQ + w], &sn, &cs);
        sm->pc[7 + w] = cs; sm->ps[7 + w] = sn;
    }
    // Pair tables: T_m for bit-pair (2m+1, 2m) = qubit pair (2k, 2k+1), k = 6-m.
    // Entry j: j bit0 = qubit b(=2k+1) state, j bit1 = qubit a(=2k) state.
    if (tid < 7) {
        const int m = tid, k = 6 - m;
        const int qa = 2 * k, qb = 2 * k + 1;
        float sa, ca, sb, cb, sx, cx;
        sincosf(0.5f * p[(b * 3 + 0) * NQ + qa], &sa, &ca);
        sincosf(0.5f * p[(b * 3 + 0) * NQ + qb], &sb, &cb);
        sincosf(0.5f * cp[b * NQ + k], &sx, &cx);
        // RX1 x RX1 on |00>
        float2 v[4] = { make_float2(ca * cb, 0.f), make_float2(0.f, -ca * sb),
                        make_float2(0.f, -sa * cb), make_float2(-sa * sb, 0.f) };
        // XX: u_j = cx*v_j + (-i sx)*v_{j^3}
        float2 u[4];
#pragma unroll
        for (int j = 0; j < 4; ++j) {
            const float2 pv = v[j], qv = v[j ^ 3];
            u[j] = make_float2(fmaf(cx, pv.x,  sx * qv.y), fmaf(cx, pv.y, -sx * qv.x));
        }
        // RZ phases
        const float tza = p[(b * 3 + 1) * NQ + qa];
        const float tzb = p[(b * 3 + 1) * NQ + qb];
#pragma unroll
        for (int j = 0; j < 4; ++j) {
            const float ang = 0.5f * (((j & 2) ? tza : -tza) + ((j & 1) ? tzb : -tzb));
            float se, ce;
            sincosf(ang, &se, &ce);
            sm->T[m][j] = cmul(u[j], make_float2(ce, se));
        }
    }
    __syncthreads();

    run_passA(sm);                                   // generate + XX(9,10),(11,12) + RX q9-12
    __syncthreads();

    {   // Pass B: XX(13,0), RX q0,q13, XX(7,8), RX q7,q8
        constexpr int gens[4] = {0x2001, 0x2000, 0x60, 0x40};
        constexpr int combos[6] = {1, 2, 3, 4, 8, 12};
        constexpr int slots[6]  = {6, 7, 20, 3, 14, 15};
        run_pass<4, 6, 0x2061>(sm, gens, combos, slots);
    }
    __syncthreads();

    {   // Pass C: XX(1,2), RX q1,q2, XX(3,4), RX q3,q4
        constexpr int gens[4] = {0x1800, 0x1000, 0x600, 0x400};
        constexpr int combos[6] = {1, 2, 3, 4, 8, 12};
        constexpr int slots[6]  = {0, 8, 9, 1, 10, 11};
        run_pass<4, 6, 0x1E00>(sm, gens, combos, slots);
    }
    __syncthreads();

    // Pass D: XX(5,6) + RX q5,q6 + fused permuted probability reduction
    float acc[NQ];
#pragma unroll
    for (int w = 0; w < NQ; ++w) acc[w] = 0.f;
    run_passD(sm, acc);

#pragma unroll
    for (int w = 0; w < NQ; ++w)
#pragma unroll
        for (int off = 16; off > 0; off >>= 1)
            acc[w] += __shfl_xor_sync(0xffffffffu, acc[w], off);

    const int warp = tid >> 5, lane = tid & 31;
    if (lane == 0) {
#pragma unroll
        for (int w = 0; w < NQ; ++w) sm->red[warp * NQ + w] = acc[w];
    }
    __syncthreads();
    if (tid < NQ) {
        float s = 0.f;
#pragma unroll
        for (int ww = 0; ww < NT / 32; ++ww) s += sm->red[ww * NQ + tid];
        out[b * NQ + tid] = s;
    }
}

} // namespace

extern "C" void kernel_launch(void* const* d_in, const int* in_sizes, int n_in,
                              void* d_out, int out_size) {
    const float* cp = (const float*)d_in[0];
    const float* p  = (const float*)d_in[1];
    float* out = (float*)d_out;
    const int B = in_sizes[0] / NQ;   // 512
    build_inv_kernel<<<NS / NT, NT>>>();
    cudaFuncSetAttribute(qsim_kernel, cudaFuncAttributeMaxDynamicSharedMemorySize,
                         (int)sizeof(Smem));
    qsim_kernel<<<B, NT, sizeof(Smem)>>>(cp, p, out);
}

// round 6
// speedup vs baseline: 2.8968x; 1.1320x over previous
#include <cuda_runtime.h>
#include <stdint.h>

namespace {

constexpr int NQ = 14;
constexpr int NS = 1 << NQ;          // 16384 amplitudes
constexpr int NT = 512;              // threads per CTA

struct Smem {
    float2 st[NS];                    // state, XOR-swizzled layout (no padding)
    float  pbuf[NS];                  // permuted probabilities
    float2 T[7][4];                   // pair tables: prefix circuit per bit-pair
    float pc[21], ps[21];             // slots 0-6 XX2 (cp col 7+s), 7-20 RX3 (qubit s-7)
    float red[(NT / 32) * NQ];
};

__device__ uint16_t g_inv[NS];       // inverse of the composed MCX permutation

__device__ __forceinline__ float2 cmul(float2 a, float2 b) {
    return make_float2(fmaf(a.x, b.x, -a.y * b.y), fmaf(a.x, b.y, a.y * b.x));
}

// XOR-linear swizzled byte offset of float2 element i: conflict-free for all passes,
// and swaddr(a^b) == swaddr(a) ^ swaddr(b)  -> orbit addresses = base ^ const.
__device__ __host__ __forceinline__ uint32_t swaddr(uint32_t i) {
    return (i << 3) ^ ((i >> 1) & 0x78u);
}

__device__ __forceinline__ float2 ld_st(const Smem* sm, uint32_t off) {
    return *reinterpret_cast<const float2*>(reinterpret_cast<const char*>(sm->st) + off);
}
__device__ __forceinline__ void st_st(Smem* sm, uint32_t off, float2 v) {
    *reinterpret_cast<float2*>(reinterpret_cast<char*>(sm->st) + off) = v;
}

// Apply NG butterfly gates; gate g pairs t <-> t^combos[g] (combo = mask over gen dims).
template<int G, int NG>
__device__ __forceinline__ void apply_gates(float2 (&a)[1 << G], const int (&combos)[NG],
                                            const float (&cg)[NG], const float (&sg)[NG]) {
#pragma unroll
    for (int g = 0; g < NG; ++g) {
        const int cb = combos[g];
        const int lb = cb & (-cb);
        const float c = cg[g], s = sg[g];
#pragma unroll
        for (int t = 0; t < (1 << G); ++t) {
            if ((t & lb) == 0) {
                const int u = t ^ cb;
                const float2 a0 = a[t], a1 = a[u];
                a[t] = make_float2(fmaf(c, a0.x,  s * a1.y), fmaf(c, a0.y, -s * a1.x));
                a[u] = make_float2(fmaf(c, a1.x,  s * a0.y), fmaf(c, a1.y, -s * a0.x));
            }
        }
    }
}

// rep formulas as functor structs (no --extended-lambda available)
struct RepB { __device__ __forceinline__ int operator()(int k) const {
    return ((k & 0xF) << 1) | ((k >> 4) << 7);   // non-span bits 1-4, 7-12
}};
struct RepC { __device__ __forceinline__ int operator()(int k) const {
    return (k & 0x1FF) | ((k >> 9) << 13);       // non-span bits 0-8, 13
}};

// Generic load-gates-store pass with caller-provided rep formula (RepF).
template<int G, int NG, class RepF>
__device__ __forceinline__ void run_pass(Smem* sm, RepF repf, const int (&gens)[G],
                                         const int (&combos)[NG], const int (&slots)[NG]) {
    constexpr int NO = 1 << G;
    float cg[NG], sg[NG];
#pragma unroll
    for (int g = 0; g < NG; ++g) { cg[g] = sm->pc[slots[g]]; sg[g] = sm->ps[slots[g]]; }
    for (int k = threadIdx.x; k < (NS >> G); k += NT) {
        const uint32_t abase = swaddr((uint32_t)repf(k));
        uint32_t aoff[NO];
#pragma unroll
        for (int t = 0; t < NO; ++t) {
            uint32_t x = 0;
#pragma unroll
            for (int g = 0; g < G; ++g) if ((t >> g) & 1) x ^= (uint32_t)gens[g];
            aoff[t] = abase ^ swaddr(x);   // swaddr(x) folds to a constant
        }
        float2 a[NO];
#pragma unroll
        for (int t = 0; t < NO; ++t) a[t] = ld_st(sm, aoff[t]);
        apply_gates<G, NG>(a, combos, cg, sg);
#pragma unroll
        for (int t = 0; t < NO; ++t) st_st(sm, aoff[t], a[t]);
    }
}

// Pass A: generate state from pair tables + XX(9,10), XX(11,12), RX q9..q12.
__device__ __forceinline__ void run_passA(Smem* sm) {
    // gens: g0=0x18(t0), g1=0x10(t1), g2=0x06(t2), g3=0x04(t3); span bits 1-4
    constexpr int combos[6] = {1, 4, 2, 3, 8, 12};  // XX(9,10),XX(11,12),RX q9,q10,q11,q12
    constexpr int slots[6]  = {4, 5, 16, 17, 18, 19};
    float cg[6], sg[6];
#pragma unroll
    for (int g = 0; g < 6; ++g) { cg[g] = sm->pc[slots[g]]; sg[g] = sm->ps[slots[g]]; }

    for (int k = threadIdx.x; k < (NS >> 4); k += NT) {
        const int rep = (k & 1) | ((k >> 1) << 5);          // non-span bits 0, 5-13
        const uint32_t abase = swaddr((uint32_t)rep);
        // amp(i) = prod_m T_m[(i>>2m)&3]; bits 5-13 fixed by rep
        const float2 base = cmul(cmul(sm->T[3][(rep >> 6) & 3], sm->T[4][(rep >> 8) & 3]),
                                 cmul(sm->T[5][(rep >> 10) & 3], sm->T[6][(rep >> 12) & 3]));
        const int b0 = rep & 1, b5 = (rep >> 5) & 1;
        const float2 q2x[2] = { cmul(base, sm->T[2][2 * b5]),
                                cmul(base, sm->T[2][1 + 2 * b5]) };   // index = bit4
        const float2 q0[2] = { sm->T[0][b0], sm->T[0][b0 + 2] };      // index = bit1
        float2 m8[2][4];
#pragma unroll
        for (int b4 = 0; b4 < 2; ++b4)
#pragma unroll
            for (int j23 = 0; j23 < 4; ++j23)
                m8[b4][j23] = cmul(q2x[b4], sm->T[1][j23]);
        float2 a[16];
#pragma unroll
        for (int t = 0; t < 16; ++t) {
            // in-span bits as functions of t: b1=t2, b2=t2^t3, b3=t0, b4=t0^t1
            const int t0 = t & 1, t1 = (t >> 1) & 1, t2 = (t >> 2) & 1, t3 = (t >> 3) & 1;
            a[t] = cmul(m8[t0 ^ t1][(t0 << 1) | (t2 ^ t3)], q0[t2]);
        }
        apply_gates<4, 6>(a, combos, cg, sg);
#pragma unroll
        for (int t = 0; t < 16; ++t) {
            uint32_t x = 0;
            if (t & 1) x ^= 0x18u;
            if (t & 2) x ^= 0x10u;
            if (t & 4) x ^= 0x06u;
            if (t & 8) x ^= 0x04u;
            st_st(sm, abase ^ swaddr(x), a[t]);
        }
    }
}

// Pass D: XX(5,6) + RX q5,q6, then scatter |amp|^2 into pbuf at permuted index.
__device__ __forceinline__ void run_passD(Smem* sm) {
    constexpr int combos[3] = {1, 2, 3};            // XX(5,6), RX q5, RX q6
    constexpr int slots[3]  = {2, 12, 13};
    constexpr int XT[4] = {0, 0x180, 0x100, 0x080};
    float cg[3], sg[3];
#pragma unroll
    for (int g = 0; g < 3; ++g) { cg[g] = sm->pc[slots[g]]; sg[g] = sm->ps[slots[g]]; }
    for (int k = threadIdx.x; k < (NS >> 2); k += NT) {
        const int rep = (k & 0x7F) | ((k >> 7) << 9);  // non-span bits 0-6, 9-13
        const uint32_t abase = swaddr((uint32_t)rep);
        float2 a[4];
#pragma unroll
        for (int t = 0; t < 4; ++t) a[t] = ld_st(sm, abase ^ swaddr((uint32_t)XT[t]));
        apply_gates<2, 3>(a, combos, cg, sg);
#pragma unroll
        for (int t = 0; t < 4; ++t) {
            const float pr = fmaf(a[t].x, a[t].x, a[t].y * a[t].y);
            const int i = (int)__ldg(&g_inv[rep ^ XT[t]]);
            sm->pbuf[i] = pr;
        }
    }
}

// Pass E: Walsh-style sign-tree reduction over natural-order probabilities.
__device__ __forceinline__ void run_passE(Smem* sm, float (&acc)[NQ]) {
    const int tid = threadIdx.x;
    float pv[32];
#pragma unroll
    for (int q = 0; q < 8; ++q) {
        const float4 v = reinterpret_cast<const float4*>(sm->pbuf)[tid * 8 + q];
        pv[4 * q + 0] = v.x; pv[4 * q + 1] = v.y; pv[4 * q + 2] = v.z; pv[4 * q + 3] = v.w;
    }
    float D0 = 0.f, D1 = 0.f, D2 = 0.f, D3 = 0.f;
    float s16[16];
#pragma unroll
    for (int i = 0; i < 16; ++i) { s16[i] = pv[2*i] + pv[2*i+1]; D0 += pv[2*i] - pv[2*i+1]; }
    float s8[8];
#pragma unroll
    for (int i = 0; i < 8; ++i)  { s8[i] = s16[2*i] + s16[2*i+1]; D1 += s16[2*i] - s16[2*i+1]; }
    float s4[4];
#pragma unroll
    for (int i = 0; i < 4; ++i)  { s4[i] = s8[2*i] + s8[2*i+1]; D2 += s8[2*i] - s8[2*i+1]; }
    float s2a[2];
#pragma unroll
    for (int i = 0; i < 2; ++i)  { s2a[i] = s4[2*i] + s4[2*i+1]; D3 += s4[2*i] - s4[2*i+1]; }
    const float S  = s2a[0] + s2a[1];
    const float D4 = s2a[0] - s2a[1];
    acc[13] = D0; acc[12] = D1; acc[11] = D2; acc[10] = D3; acc[9] = D4;
    // bits 5..13 of index j = tid bits 0..8; qubit w = 13 - b
#pragma unroll
    for (int bb = 5; bb <= 13; ++bb)
        acc[13 - bb] = ((tid >> (bb - 5)) & 1) ? -S : S;
}

__global__ void build_inv_kernel() {
    const int i = blockIdx.x * blockDim.x + threadIdx.x;
    int j = i;
#pragma unroll
    for (int w = NQ - 1; w >= 0; --w) {
        const int c1 = NQ - 1 - w;
        const int c2 = NQ - 1 - ((w + 1) % NQ);
        const int tt = NQ - 1 - ((w + 2) % NQ);
        const int b1 = (j >> c1) & 1;
        const int b2 = (j >> c2) & 1;
        if (b1 & (b2 ^ 1)) j ^= (1 << tt);
    }
    g_inv[j] = (uint16_t)i;   // composite(i) = j  =>  inv[j] = i (bijection, no race)
}

__global__ __launch_bounds__(NT, 1)
void qsim_kernel(const float* __restrict__ cp, const float* __restrict__ p,
                 float* __restrict__ out) {
    extern __shared__ char smraw[];
    Smem* sm = reinterpret_cast<Smem*>(smraw);
    const int tid = threadIdx.x;
    const int b = blockIdx.x;

    if (tid < NQ) {
        const int w = tid;
        float sn, cs;
        if (w >= 7) {
            sincosf(0.5f * cp[b * NQ + w], &sn, &cs);
            sm->pc[w - 7] = cs; sm->ps[w - 7] = sn;
        }
        sincosf(0.5f * p[(b * 3 + 2) * NQ + w], &sn, &cs);
        sm->pc[7 + w] = cs; sm->ps[7 + w] = sn;
    }
    // Pair tables: T_m for bit-pair (2m+1, 2m) = qubit pair (2k, 2k+1), k = 6-m.
    if (tid < 7) {
        const int m = tid, k = 6 - m;
        const int qa = 2 * k, qb = 2 * k + 1;
        float sa, ca, sb, cb, sx, cx;
        sincosf(0.5f * p[(b * 3 + 0) * NQ + qa], &sa, &ca);
        sincosf(0.5f * p[(b * 3 + 0) * NQ + qb], &sb, &cb);
        sincosf(0.5f * cp[b * NQ + k], &sx, &cx);
        float2 v[4] = { make_float2(ca * cb, 0.f), make_float2(0.f, -ca * sb),
                        make_float2(0.f, -sa * cb), make_float2(-sa * sb, 0.f) };
        float2 u[4];
#pragma unroll
        for (int j = 0; j < 4; ++j) {
            const float2 pv = v[j], qv = v[j ^ 3];
            u[j] = make_float2(fmaf(cx, pv.x,  sx * qv.y), fmaf(cx, pv.y, -sx * qv.x));
        }
        const float tza = p[(b * 3 + 1) * NQ + qa];
        const float tzb = p[(b * 3 + 1) * NQ + qb];
#pragma unroll
        for (int j = 0; j < 4; ++j) {
            const float ang = 0.5f * (((j & 2) ? tza : -tza) + ((j & 1) ? tzb : -tzb));
            float se, ce;
            sincosf(ang, &se, &ce);
            sm->T[m][j] = cmul(u[j], make_float2(ce, se));
        }
    }
    __syncthreads();

    run_passA(sm);                                   // generate + XX(9,10),(11,12) + RX q9-12
    __syncthreads();

    {   // Pass B: XX(13,0), RX q0,q13, XX(7,8), RX q7,q8
        constexpr int gens[4] = {0x2001, 0x2000, 0x60, 0x40};
        constexpr int combos[6] = {1, 2, 3, 4, 8, 12};
        constexpr int slots[6]  = {6, 7, 20, 3, 14, 15};
        run_pass<4, 6>(sm, RepB{}, gens, combos, slots);
    }
    __syncthreads();

    {   // Pass C: XX(1,2), RX q1,q2, XX(3,4), RX q3,q4
        constexpr int gens[4] = {0x1800, 0x1000, 0x600, 0x400};
        constexpr int combos[6] = {1, 2, 3, 4, 8, 12};
        constexpr int slots[6]  = {0, 8, 9, 1, 10, 11};
        run_pass<4, 6>(sm, RepC{}, gens, combos, slots);
    }
    __syncthreads();

    run_passD(sm);                                   // XX(5,6)+RX q5,q6 + prob scatter
    __syncthreads();

    float acc[NQ];
    run_passE(sm, acc);                              // sign-tree reduction

#pragma unroll
    for (int w = 0; w < NQ; ++w)
#pragma unroll
        for (int off = 16; off > 0; off >>= 1)
            acc[w] += __shfl_xor_sync(0xffffffffu, acc[w], off);

    const int warp = tid >> 5, lane = tid & 31;
    if (lane == 0) {
#pragma unroll
        for (int w = 0; w < NQ; ++w) sm->red[warp * NQ + w] = acc[w];
    }
    __syncthreads();
    if (tid < NQ) {
        float s = 0.f;
#pragma unroll
        for (int ww = 0; ww < NT / 32; ++ww) s += sm->red[ww * NQ + tid];
        out[b * NQ + tid] = s;
    }
}

} // namespace

extern "C" void kernel_launch(void* const* d_in, const int* in_sizes, int n_in,
                              void* d_out, int out_size) {
    const float* cp = (const float*)d_in[0];
    const float* p  = (const float*)d_in[1];
    float* out = (float*)d_out;
    const int B = in_sizes[0] / NQ;   // 512
    build_inv_kernel<<<NS / NT, NT>>>();
    cudaFuncSetAttribute(qsim_kernel, cudaFuncAttributeMaxDynamicSharedMemorySize,
                         (int)sizeof(Smem));
    qsim_kernel<<<B, NT, sizeof(Smem)>>>(cp, p, out);
}